// round 1
// baseline (speedup 1.0000x reference)
#include <cuda_runtime.h>
#include <math.h>
#include <stdint.h>

// ---------------------------------------------------------------------------
// Problem constants
// ---------------------------------------------------------------------------
#define HW      64          // H = W = 64
#define CSZ     512
#define BSZ     32
#define MROWS   131072      // H*W*B = 4096*32
#define NHEAD   16
#define DHEAD   32

// ---------------------------------------------------------------------------
// Scratch (static device globals -- no allocations allowed)
// ---------------------------------------------------------------------------
__device__ float g_xw    [(size_t)MROWS * CSZ];    // LN1 + shift + window-partition output
__device__ float g_ctx   [(size_t)MROWS * CSZ];    // attention context
__device__ float g_hidden[(size_t)MROWS * CSZ];    // post-attention residual (original layout)
__device__ float g_ln2   [(size_t)MROWS * CSZ];    // LN2 output
__device__ float g_big   [(size_t)MROWS * 2048];   // qkv (stride 1536), then fc1 out (stride 2048)

// ---------------------------------------------------------------------------
// LayerNorm (+ optional shift/window-partition gather)
//   permute==1: block r is the *output* row of xw; gathers from shifted image
//   permute==0: identity rows (hidden -> ln2)
// ---------------------------------------------------------------------------
__global__ __launch_bounds__(128) void k_ln(const float* __restrict__ x,
                                            const float* __restrict__ g,
                                            const float* __restrict__ b,
                                            float* __restrict__ y,
                                            int permute)
{
    int r = blockIdx.x;
    int src = r;
    if (permute) {
        int s  = r >> 11;          // window index (hn*8+wn)
        int n  = r & 2047;         // (i*8+j)*32 + batch
        int hn = s >> 3, wn = s & 7;
        int ij = n >> 5, bb = n & 31;
        int i  = ij >> 3, j = ij & 7;
        int h  = ((hn << 3) + i + 4) & 63;   // roll(-4) gather
        int w  = ((wn << 3) + j + 4) & 63;
        src = ((h << 6) + w) * 32 + bb;
    }
    int t = threadIdx.x;  // 128 threads, 4 floats each
    const float4* xin = (const float4*)(x + (long)src * CSZ);
    float4 v = xin[t];
    float sum = v.x + v.y + v.z + v.w;
    float sq  = v.x*v.x + v.y*v.y + v.z*v.z + v.w*v.w;
    #pragma unroll
    for (int o = 16; o > 0; o >>= 1) {
        sum += __shfl_xor_sync(0xffffffffu, sum, o);
        sq  += __shfl_xor_sync(0xffffffffu, sq,  o);
    }
    __shared__ float ssum[4], ssq[4];
    int warp = t >> 5, lane = t & 31;
    if (lane == 0) { ssum[warp] = sum; ssq[warp] = sq; }
    __syncthreads();
    float tot = ssum[0] + ssum[1] + ssum[2] + ssum[3];
    float tq  = ssq[0]  + ssq[1]  + ssq[2]  + ssq[3];
    float mu  = tot * (1.0f / 512.0f);
    float var = tq * (1.0f / 512.0f) - mu * mu;
    float inv = rsqrtf(var + 1e-5f);
    float4 gg = ((const float4*)g)[t];
    float4 bb4 = ((const float4*)b)[t];
    float4 o;
    o.x = (v.x - mu) * inv * gg.x + bb4.x;
    o.y = (v.y - mu) * inv * gg.y + bb4.y;
    o.z = (v.z - mu) * inv * gg.z + bb4.z;
    o.w = (v.w - mu) * inv * gg.w + bb4.w;
    ((float4*)(y + (long)r * CSZ))[t] = o;
}

// ---------------------------------------------------------------------------
// Windowed attention: one block per (n, head). 64x64 scores over DH=32.
// ---------------------------------------------------------------------------
__device__ __forceinline__ int regcode(int h) { return h < 56 ? 0 : (h < 60 ? 1 : 2); }

__global__ __launch_bounds__(256) void k_attn(const float* __restrict__ qkv,
                                              float* __restrict__ ctx)
{
    int n  = blockIdx.x >> 4;
    int hd = blockIdx.x & 15;

    __shared__ float sq[64][33], sk[64][33], sv[64][33];
    __shared__ float sp[64][65];

    int tid = threadIdx.x;
    for (int idx = tid; idx < 2048; idx += 256) {
        int s = idx >> 5, d = idx & 31;
        long base = ((long)(s * 2048 + n)) * 1536 + hd * 96 + d;
        sq[s][d] = qkv[base];
        sk[s][d] = qkv[base + 32];
        sv[s][d] = qkv[base + 64];
    }
    __syncthreads();

    int nw = n & 63;
    int s  = tid >> 2;
    int t0 = (tid & 3) << 4;

    float qr[32];
    #pragma unroll
    for (int d = 0; d < 32; d++) qr[d] = sq[s][d];

    int cs = regcode(((nw >> 3) << 3) + (s >> 3)) * 3 + regcode(((nw & 7) << 3) + (s & 7));

    float sc[16];
    float mx = -1e30f;
    #pragma unroll
    for (int tt = 0; tt < 16; tt++) {
        int t = t0 + tt;
        float a = 0.0f;
        #pragma unroll
        for (int d = 0; d < 32; d++) a += qr[d] * sk[t][d];
        a *= 0.17677669529663689f;   // 1/sqrt(32)
        int ct = regcode(((nw >> 3) << 3) + (t >> 3)) * 3 + regcode(((nw & 7) << 3) + (t & 7));
        a = (ct != cs) ? -10000.0f : a;
        sc[tt] = a;
        mx = fmaxf(mx, a);
    }
    mx = fmaxf(mx, __shfl_xor_sync(0xffffffffu, mx, 1));
    mx = fmaxf(mx, __shfl_xor_sync(0xffffffffu, mx, 2));
    float sum = 0.0f;
    #pragma unroll
    for (int tt = 0; tt < 16; tt++) { sc[tt] = expf(sc[tt] - mx); sum += sc[tt]; }
    sum += __shfl_xor_sync(0xffffffffu, sum, 1);
    sum += __shfl_xor_sync(0xffffffffu, sum, 2);
    float inv = 1.0f / sum;
    #pragma unroll
    for (int tt = 0; tt < 16; tt++) sp[s][t0 + tt] = sc[tt] * inv;
    __syncthreads();

    int d0 = (tid & 3) << 3;
    float acc[8];
    #pragma unroll
    for (int d = 0; d < 8; d++) acc[d] = 0.0f;
    for (int t = 0; t < 64; t++) {
        float p = sp[s][t];
        #pragma unroll
        for (int d = 0; d < 8; d++) acc[d] += p * sv[t][d0 + d];
    }
    long ob = ((long)(s * 2048 + n)) * 512 + hd * 32 + d0;
    #pragma unroll
    for (int d = 0; d < 8; d++) ctx[ob + d] = acc[d];
}

// ---------------------------------------------------------------------------
// Tiled SGEMM: C = A[MxK] * B[KxN] (+epilogue).  BM=BN=128, BK=16, 256 thr, 8x8.
//   EPI 0: C[r*N+c]  = acc + bias[c]                           (QKV)
//   EPI 1: scatter:   hidden[dest,c] = acc+bias+xw[r,c]+shortcut[dest,c]
//   EPI 2: C[r*N+c]  = gelu(acc + bias[c])                     (FC1)
//   EPI 3: C[r*N+c]  = acc + bias[c] + add1[r,c] + add2[r,c]   (FC2 final)
// ---------------------------------------------------------------------------
#define BM 128
#define BN 128
#define BK 16

__device__ __forceinline__ float gelu_exact(float x)
{
    return 0.5f * x * (1.0f + erff(x * 0.70710678118654752f));
}

template <int EPI>
__global__ __launch_bounds__(256) void sgemm(const float* __restrict__ A,
                                             const float* __restrict__ B,
                                             const float* __restrict__ bias,
                                             float* __restrict__ C,
                                             const float* __restrict__ add1,
                                             const float* __restrict__ add2,
                                             int N, int K)
{
    __shared__ float As[BK][BM];
    __shared__ float Bs[BK][BN];

    int tid = threadIdx.x;
    int ty = tid >> 4, tx = tid & 15;

    // gmem load indices
    int arow = tid >> 2;            // 0..63
    int acol = (tid & 3) << 2;      // 0,4,8,12
    int brow = tid >> 5;            // 0..7
    int bcol = (tid & 31) << 2;     // 0..124

    long rowBlk = (long)blockIdx.y * BM;
    int  colBlk = blockIdx.x * BN;

    const float* Aa = A + rowBlk * K;
    const float* Bb = B + colBlk;

    float acc[8][8];
    #pragma unroll
    for (int i = 0; i < 8; i++)
        #pragma unroll
        for (int j = 0; j < 8; j++) acc[i][j] = 0.0f;

    int kTiles = K / BK;
    for (int kt = 0; kt < kTiles; kt++) {
        const float4 a0 = *(const float4*)&Aa[(long)(arow)      * K + kt * BK + acol];
        const float4 a1 = *(const float4*)&Aa[(long)(arow + 64) * K + kt * BK + acol];
        const float4 b0 = *(const float4*)&Bb[(long)(kt * BK + brow)     * N + bcol];
        const float4 b1 = *(const float4*)&Bb[(long)(kt * BK + brow + 8) * N + bcol];

        __syncthreads();
        As[acol + 0][arow]      = a0.x;
        As[acol + 1][arow]      = a0.y;
        As[acol + 2][arow]      = a0.z;
        As[acol + 3][arow]      = a0.w;
        As[acol + 0][arow + 64] = a1.x;
        As[acol + 1][arow + 64] = a1.y;
        As[acol + 2][arow + 64] = a1.z;
        As[acol + 3][arow + 64] = a1.w;
        *(float4*)&Bs[brow][bcol]     = b0;
        *(float4*)&Bs[brow + 8][bcol] = b1;
        __syncthreads();

        #pragma unroll
        for (int k = 0; k < BK; k++) {
            float a[8], b[8];
            *(float4*)&a[0] = *(const float4*)&As[k][ty * 8];
            *(float4*)&a[4] = *(const float4*)&As[k][ty * 8 + 4];
            *(float4*)&b[0] = *(const float4*)&Bs[k][tx * 8];
            *(float4*)&b[4] = *(const float4*)&Bs[k][tx * 8 + 4];
            #pragma unroll
            for (int i = 0; i < 8; i++)
                #pragma unroll
                for (int j = 0; j < 8; j++) acc[i][j] += a[i] * b[j];
        }
    }

    // ----- epilogue -----
    int col0 = colBlk + tx * 8;
    float4 bias0 = *(const float4*)&bias[col0];
    float4 bias1 = *(const float4*)&bias[col0 + 4];

    #pragma unroll
    for (int i = 0; i < 8; i++) {
        long r = rowBlk + ty * 8 + i;
        float4 v0, v1;
        v0.x = acc[i][0] + bias0.x; v0.y = acc[i][1] + bias0.y;
        v0.z = acc[i][2] + bias0.z; v0.w = acc[i][3] + bias0.w;
        v1.x = acc[i][4] + bias1.x; v1.y = acc[i][5] + bias1.y;
        v1.z = acc[i][6] + bias1.z; v1.w = acc[i][7] + bias1.w;

        if (EPI == 0) {
            *(float4*)&C[r * N + col0]     = v0;
            *(float4*)&C[r * N + col0 + 4] = v1;
        } else if (EPI == 1) {
            int s  = (int)(r >> 11), n = (int)(r & 2047);
            int hn = s >> 3, wn = s & 7;
            int ij = n >> 5, bb = n & 31;
            int h  = ((hn << 3) + (ij >> 3) + 4) & 63;   // window-reverse + roll(+4)
            int w  = ((wn << 3) + (ij & 7) + 4) & 63;
            long dest = ((long)(((h << 6) + w) * 32 + bb)) * 512;
            long src1 = r * 512;
            float4 x0 = *(const float4*)&add1[src1 + col0];
            float4 x1 = *(const float4*)&add1[src1 + col0 + 4];
            float4 s0 = *(const float4*)&add2[dest + col0];
            float4 s1 = *(const float4*)&add2[dest + col0 + 4];
            v0.x += x0.x + s0.x; v0.y += x0.y + s0.y; v0.z += x0.z + s0.z; v0.w += x0.w + s0.w;
            v1.x += x1.x + s1.x; v1.y += x1.y + s1.y; v1.z += x1.z + s1.z; v1.w += x1.w + s1.w;
            *(float4*)&C[dest + col0]     = v0;
            *(float4*)&C[dest + col0 + 4] = v1;
        } else if (EPI == 2) {
            v0.x = gelu_exact(v0.x); v0.y = gelu_exact(v0.y);
            v0.z = gelu_exact(v0.z); v0.w = gelu_exact(v0.w);
            v1.x = gelu_exact(v1.x); v1.y = gelu_exact(v1.y);
            v1.z = gelu_exact(v1.z); v1.w = gelu_exact(v1.w);
            *(float4*)&C[r * N + col0]     = v0;
            *(float4*)&C[r * N + col0 + 4] = v1;
        } else {
            long base = r * N;
            float4 h0 = *(const float4*)&add1[base + col0];
            float4 h1 = *(const float4*)&add1[base + col0 + 4];
            float4 l0 = *(const float4*)&add2[base + col0];
            float4 l1 = *(const float4*)&add2[base + col0 + 4];
            v0.x += h0.x + l0.x; v0.y += h0.y + l0.y; v0.z += h0.z + l0.z; v0.w += h0.w + l0.w;
            v1.x += h1.x + l1.x; v1.y += h1.y + l1.y; v1.z += h1.z + l1.z; v1.w += h1.w + l1.w;
            *(float4*)&C[base + col0]     = v0;
            *(float4*)&C[base + col0 + 4] = v1;
        }
    }
}

// ---------------------------------------------------------------------------
// Launcher
// ---------------------------------------------------------------------------
extern "C" void kernel_launch(void* const* d_in, const int* in_sizes, int n_in,
                              void* d_out, int out_size)
{
    const float* hs    = (const float*)d_in[0];
    const float* ln1g  = (const float*)d_in[1];
    const float* ln1b  = (const float*)d_in[2];
    const float* wqkv  = (const float*)d_in[3];
    const float* bqkv  = (const float*)d_in[4];
    const float* wproj = (const float*)d_in[5];
    const float* bproj = (const float*)d_in[6];
    const float* ln2g  = (const float*)d_in[7];
    const float* ln2b  = (const float*)d_in[8];
    const float* wfc1  = (const float*)d_in[9];
    const float* bfc1  = (const float*)d_in[10];
    const float* wfc2  = (const float*)d_in[11];
    const float* bfc2  = (const float*)d_in[12];
    float* out = (float*)d_out;

    float *xw, *ctx, *hidden, *ln2buf, *big;
    cudaGetSymbolAddress((void**)&xw,     g_xw);
    cudaGetSymbolAddress((void**)&ctx,    g_ctx);
    cudaGetSymbolAddress((void**)&hidden, g_hidden);
    cudaGetSymbolAddress((void**)&ln2buf, g_ln2);
    cudaGetSymbolAddress((void**)&big,    g_big);

    // 1) LN1 + shift + window partition
    k_ln<<<MROWS, 128>>>(hs, ln1g, ln1b, xw, 1);

    // 2) QKV GEMM: [131072,512] x [512,1536]
    sgemm<0><<<dim3(1536 / BN, MROWS / BM), 256>>>(xw, wqkv, bqkv, big, nullptr, nullptr, 1536, 512);

    // 3) Windowed attention
    k_attn<<<2048 * 16, 256>>>(big, ctx);

    // 4) Proj GEMM + residual + window-reverse/unshift scatter + shortcut
    sgemm<1><<<dim3(512 / BN, MROWS / BM), 256>>>(ctx, wproj, bproj, hidden, xw, hs, 512, 512);

    // 5) LN2
    k_ln<<<MROWS, 128>>>(hidden, ln2g, ln2b, ln2buf, 0);

    // 6) FC1 GEMM + GELU: [131072,512] x [512,2048]
    sgemm<2><<<dim3(2048 / BN, MROWS / BM), 256>>>(ln2buf, wfc1, bfc1, big, nullptr, nullptr, 2048, 512);

    // 7) FC2 GEMM + final residuals: [131072,2048] x [2048,512]
    sgemm<3><<<dim3(512 / BN, MROWS / BM), 256>>>(big, wfc2, bfc2, out, hidden, ln2buf, 512, 2048);
}

// round 3
// speedup vs baseline: 2.1779x; 2.1779x over previous
#include <cuda_runtime.h>
#include <math.h>
#include <stdint.h>

// ---------------------------------------------------------------------------
// Problem constants
// ---------------------------------------------------------------------------
#define CSZ     512
#define MROWS   131072      // H*W*B = 4096*32

// ---------------------------------------------------------------------------
// Scratch (static device globals -- no allocations allowed)
// ---------------------------------------------------------------------------
__device__ float g_xw    [(size_t)MROWS * CSZ];
__device__ float g_ctx   [(size_t)MROWS * CSZ];
__device__ float g_hidden[(size_t)MROWS * CSZ];
__device__ float g_ln2   [(size_t)MROWS * CSZ];
__device__ float g_big   [(size_t)MROWS * 2048];
// preformatted (fragment-ordered, tf32-rounded) weights
__device__ float g_wprep [512*1536 + 512*512 + 512*2048 + 2048*512];

#define WP_QKV  0
#define WP_PROJ (512*1536)
#define WP_FC1  (WP_PROJ + 512*512)
#define WP_FC2  (WP_FC1 + 512*2048)

// ---------------------------------------------------------------------------
// Helpers
// ---------------------------------------------------------------------------
__device__ __forceinline__ uint32_t smem_u32(const void* p) {
    uint32_t a;
    asm("{ .reg .u64 t; cvta.to.shared.u64 t, %1; cvt.u32.u64 %0, t; }" : "=r"(a) : "l"(p));
    return a;
}
__device__ __forceinline__ uint32_t cvt_tf32(float x) {
    uint32_t r;
    asm("cvt.rna.tf32.f32 %0, %1;" : "=r"(r) : "f"(x));
    return r;
}
__device__ __forceinline__ void mma_tf32(float* d, uint32_t a0, uint32_t a1, uint32_t a2, uint32_t a3,
                                         uint32_t b0, uint32_t b1)
{
    asm volatile(
        "mma.sync.aligned.m16n8k8.row.col.f32.tf32.tf32.f32 "
        "{%0,%1,%2,%3}, {%4,%5,%6,%7}, {%8,%9}, {%0,%1,%2,%3};"
        : "+f"(d[0]), "+f"(d[1]), "+f"(d[2]), "+f"(d[3])
        : "r"(a0), "r"(a1), "r"(a2), "r"(a3), "r"(b0), "r"(b1));
}

__device__ __forceinline__ float gelu_exact(float x)
{
    return 0.5f * x * (1.0f + erff(x * 0.70710678118654752f));
}

// ---------------------------------------------------------------------------
// Weight prep: W[K,N] row-major -> per (ntile j, kchunk kt) 4096-float blocks
// in B-fragment order:
//   f = ((((wc*4+ks)*4)+nt)*32 + t)*2 + which
//   n_local = wc*32 + nt*8 + (t>>2),  k_local = ks*8 + which*4 + (t&3)
// grid = (nTiles, kChunks), 256 threads.
// ---------------------------------------------------------------------------
__global__ __launch_bounds__(256) void k_prep(const float* __restrict__ W,
                                              float* __restrict__ dst,
                                              int N, int kTiles)
{
    int j = blockIdx.x, kt = blockIdx.y;
    float* blk = dst + ((size_t)(j * kTiles + kt)) * 4096;
    for (int f = threadIdx.x; f < 4096; f += 256) {
        int which = f & 1;
        int t  = (f >> 1) & 31;
        int nt = (f >> 6) & 3;
        int ks = (f >> 8) & 3;
        int wc = (f >> 10) & 3;
        int n_local = wc * 32 + nt * 8 + (t >> 2);
        int k_local = ks * 8 + which * 4 + (t & 3);
        float v = W[(size_t)(kt * 32 + k_local) * N + j * 128 + n_local];
        ((uint32_t*)blk)[f] = cvt_tf32(v);
    }
}

// ---------------------------------------------------------------------------
// LayerNorm (+ optional shift/window-partition gather)
// ---------------------------------------------------------------------------
__global__ __launch_bounds__(128) void k_ln(const float* __restrict__ x,
                                            const float* __restrict__ g,
                                            const float* __restrict__ b,
                                            float* __restrict__ y,
                                            int permute)
{
    int r = blockIdx.x;
    int src = r;
    if (permute) {
        int s  = r >> 11, n = r & 2047;
        int hn = s >> 3, wn = s & 7;
        int ij = n >> 5, bb = n & 31;
        int h  = ((hn << 3) + (ij >> 3) + 4) & 63;
        int w  = ((wn << 3) + (ij & 7) + 4) & 63;
        src = ((h << 6) + w) * 32 + bb;
    }
    int t = threadIdx.x;
    float4 v = ((const float4*)(x + (long)src * CSZ))[t];
    float sum = v.x + v.y + v.z + v.w;
    float sq  = v.x*v.x + v.y*v.y + v.z*v.z + v.w*v.w;
    #pragma unroll
    for (int o = 16; o > 0; o >>= 1) {
        sum += __shfl_xor_sync(0xffffffffu, sum, o);
        sq  += __shfl_xor_sync(0xffffffffu, sq,  o);
    }
    __shared__ float ssum[4], ssq[4];
    int warp = t >> 5, lane = t & 31;
    if (lane == 0) { ssum[warp] = sum; ssq[warp] = sq; }
    __syncthreads();
    float tot = ssum[0] + ssum[1] + ssum[2] + ssum[3];
    float tq  = ssq[0]  + ssq[1]  + ssq[2]  + ssq[3];
    float mu  = tot * (1.0f / 512.0f);
    float var = tq * (1.0f / 512.0f) - mu * mu;
    float inv = rsqrtf(var + 1e-5f);
    float4 gg = ((const float4*)g)[t];
    float4 bb4 = ((const float4*)b)[t];
    float4 o;
    o.x = (v.x - mu) * inv * gg.x + bb4.x;
    o.y = (v.y - mu) * inv * gg.y + bb4.y;
    o.z = (v.z - mu) * inv * gg.z + bb4.z;
    o.w = (v.w - mu) * inv * gg.w + bb4.w;
    ((float4*)(y + (long)r * CSZ))[t] = o;
}

// ---------------------------------------------------------------------------
// Windowed attention (fp32 SIMT)
// ---------------------------------------------------------------------------
__device__ __forceinline__ int regcode(int h) { return h < 56 ? 0 : (h < 60 ? 1 : 2); }

__global__ __launch_bounds__(256) void k_attn(const float* __restrict__ qkv,
                                              float* __restrict__ ctx)
{
    int n  = blockIdx.x >> 4;
    int hd = blockIdx.x & 15;

    __shared__ float sq[64][33], sk[64][33], sv[64][33];
    __shared__ float sp[64][65];

    int tid = threadIdx.x;
    for (int idx = tid; idx < 2048; idx += 256) {
        int s = idx >> 5, d = idx & 31;
        long base = ((long)(s * 2048 + n)) * 1536 + hd * 96 + d;
        sq[s][d] = qkv[base];
        sk[s][d] = qkv[base + 32];
        sv[s][d] = qkv[base + 64];
    }
    __syncthreads();

    int nw = n & 63;
    int s  = tid >> 2;
    int t0 = (tid & 3) << 4;

    float qr[32];
    #pragma unroll
    for (int d = 0; d < 32; d++) qr[d] = sq[s][d];

    int cs = regcode(((nw >> 3) << 3) + (s >> 3)) * 3 + regcode(((nw & 7) << 3) + (s & 7));

    float sc[16];
    float mx = -1e30f;
    #pragma unroll
    for (int tt = 0; tt < 16; tt++) {
        int t = t0 + tt;
        float a = 0.0f;
        #pragma unroll
        for (int d = 0; d < 32; d++) a += qr[d] * sk[t][d];
        a *= 0.17677669529663689f;
        int ct = regcode(((nw >> 3) << 3) + (t >> 3)) * 3 + regcode(((nw & 7) << 3) + (t & 7));
        a = (ct != cs) ? -10000.0f : a;
        sc[tt] = a;
        mx = fmaxf(mx, a);
    }
    mx = fmaxf(mx, __shfl_xor_sync(0xffffffffu, mx, 1));
    mx = fmaxf(mx, __shfl_xor_sync(0xffffffffu, mx, 2));
    float sum = 0.0f;
    #pragma unroll
    for (int tt = 0; tt < 16; tt++) { sc[tt] = expf(sc[tt] - mx); sum += sc[tt]; }
    sum += __shfl_xor_sync(0xffffffffu, sum, 1);
    sum += __shfl_xor_sync(0xffffffffu, sum, 2);
    float inv = 1.0f / sum;
    #pragma unroll
    for (int tt = 0; tt < 16; tt++) sp[s][t0 + tt] = sc[tt] * inv;
    __syncthreads();

    int d0 = (tid & 3) << 3;
    float acc[8];
    #pragma unroll
    for (int d = 0; d < 8; d++) acc[d] = 0.0f;
    for (int t = 0; t < 64; t++) {
        float p = sp[s][t];
        #pragma unroll
        for (int d = 0; d < 8; d++) acc[d] += p * sv[t][d0 + d];
    }
    long ob = ((long)(s * 2048 + n)) * 512 + hd * 32 + d0;
    #pragma unroll
    for (int d = 0; d < 8; d++) ctx[ob + d] = acc[d];
}

// ---------------------------------------------------------------------------
// tf32 mma.sync GEMM: C = A[M,K] * W[K,N] (+epilogue), 128x128 per CTA.
// 8 warps in 2x4 grid; warp tile 64x32 (4 m16 x 4 n8 frags).
// SMEM fragment-order staging for both operands; B preformatted in gmem.
//   EPI 0: out = acc + bias                                  (QKV)
//   EPI 1: scatter: C[dest] = acc+bias+add1[r]+add2[dest]    (proj)
//   EPI 2: out = gelu(acc + bias)                            (FC1)
//   EPI 3: out = acc + bias + add1[r] + add2[r]              (FC2 final)
// ---------------------------------------------------------------------------
#define DYN_SMEM (1024 + 128*132*4)   // 68608; buffers live at [1024, 66560)

template <int EPI>
__global__ __launch_bounds__(256) void gemm_tc(const float* __restrict__ A,
                                               const float* __restrict__ Bprep,
                                               const float* __restrict__ bias,
                                               float* __restrict__ C,
                                               const float* __restrict__ add1,
                                               const float* __restrict__ add2,
                                               int N, int kTiles)
{
    extern __shared__ char smem[];
    const uint32_t sbase = smem_u32(smem);
    const int tid  = threadIdx.x;
    const int wid  = tid >> 5;
    const int lane = tid & 31;
    const int wm   = wid >> 2;   // 0..1  (m band: 64 rows)
    const int wc   = wid & 3;    // 0..3  (n band: 32 cols)
    const int K = kTiles * 32;

    const long rowBlk = (long)blockIdx.y * 128;
    const int  colBlk = blockIdx.x * 128;
    const float* Bblk = Bprep + ((size_t)blockIdx.x * kTiles) * 4096;

    float acc[16][4];
    #pragma unroll
    for (int i = 0; i < 16; i++)
        #pragma unroll
        for (int j = 0; j < 4; j++) acc[i][j] = 0.0f;

    // loader indices (4 float4 each for A and B)
    // A: idx = tid + i*256 over 1024 f4s: r=idx>>3 (0..127), c4=idx&7 (k-f4)
    // fragment scatter precompute per i:
    //   mt=r>>4, ri=r&15, g=ri&7, k0=c4*4, ks=k0>>3,
    //   regbase=((ri>>3)&1)|((k0&4)?2:0)
    //   word addr = (mt*4+ks)*512 + g*64 + j*16 + regbase*4   (bytes)

    // prologue: load kt=0
    {
        const uint32_t aBase = sbase + 1024;
        const uint32_t bBase = aBase + 16384;
        #pragma unroll
        for (int i = 0; i < 4; i++) {
            int idx = tid + i * 256;
            int r = idx >> 3, c4 = idx & 7;
            float4 av = *(const float4*)&A[(rowBlk + r) * K + c4 * 4];
            int mt = r >> 4, ri = r & 15, g = ri & 7;
            int k0 = c4 * 4, ks = k0 >> 3;
            int regbase = ((ri >> 3) & 1) | ((k0 & 4) ? 2 : 0);
            uint32_t base = aBase + (uint32_t)((mt * 4 + ks) * 512 + g * 64 + regbase * 4);
            asm volatile("st.shared.b32 [%0], %1;" :: "r"(base +  0), "r"(cvt_tf32(av.x)) : "memory");
            asm volatile("st.shared.b32 [%0], %1;" :: "r"(base + 16), "r"(cvt_tf32(av.y)) : "memory");
            asm volatile("st.shared.b32 [%0], %1;" :: "r"(base + 32), "r"(cvt_tf32(av.z)) : "memory");
            asm volatile("st.shared.b32 [%0], %1;" :: "r"(base + 48), "r"(cvt_tf32(av.w)) : "memory");
        }
        const float4* bp = (const float4*)Bblk;
        #pragma unroll
        for (int i = 0; i < 4; i++) {
            float4 bv = bp[tid + i * 256];
            asm volatile("st.shared.v4.b32 [%0], {%1,%2,%3,%4};"
                         :: "r"(bBase + (uint32_t)(tid + i * 256) * 16),
                            "r"(__float_as_uint(bv.x)), "r"(__float_as_uint(bv.y)),
                            "r"(__float_as_uint(bv.z)), "r"(__float_as_uint(bv.w)) : "memory");
        }
    }
    __syncthreads();

    for (int kt = 0; kt < kTiles; kt++) {
        const int b = kt & 1;
        const uint32_t aBase = sbase + 1024 + b * 32768;
        const uint32_t bBase = aBase + 16384;
        const int nb = (kt + 1) & 1;
        const uint32_t aBaseN = sbase + 1024 + nb * 32768;
        const uint32_t bBaseN = aBaseN + 16384;

        // issue gmem loads for next chunk
        float4 av[4], bv[4];
        const bool more = (kt + 1 < kTiles);
        if (more) {
            #pragma unroll
            for (int i = 0; i < 4; i++) {
                int idx = tid + i * 256;
                int r = idx >> 3, c4 = idx & 7;
                av[i] = *(const float4*)&A[(rowBlk + r) * K + (kt + 1) * 32 + c4 * 4];
            }
            const float4* bp = (const float4*)(Bblk + (size_t)(kt + 1) * 4096);
            #pragma unroll
            for (int i = 0; i < 4; i++) bv[i] = bp[tid + i * 256];
        }

        // compute on current buffers
        #pragma unroll
        for (int ks = 0; ks < 4; ks++) {
            uint32_t afr[4][4];
            #pragma unroll
            for (int mi = 0; mi < 4; mi++) {
                uint32_t addr = aBase + (uint32_t)(((wm * 4 + mi) * 4 + ks) * 512 + lane * 16);
                asm volatile("ld.shared.v4.b32 {%0,%1,%2,%3}, [%4];"
                             : "=r"(afr[mi][0]), "=r"(afr[mi][1]), "=r"(afr[mi][2]), "=r"(afr[mi][3])
                             : "r"(addr));
            }
            uint32_t bfr[4][2];
            #pragma unroll
            for (int nt = 0; nt < 4; nt++) {
                uint32_t addr = bBase + (uint32_t)((((wc * 4 + ks) * 4 + nt) * 32 + lane) * 8);
                asm volatile("ld.shared.v2.b32 {%0,%1}, [%2];"
                             : "=r"(bfr[nt][0]), "=r"(bfr[nt][1]) : "r"(addr));
            }
            #pragma unroll
            for (int mi = 0; mi < 4; mi++)
                #pragma unroll
                for (int nt = 0; nt < 4; nt++)
                    mma_tf32(acc[mi * 4 + nt], afr[mi][0], afr[mi][1], afr[mi][2], afr[mi][3],
                             bfr[nt][0], bfr[nt][1]);
        }

        // store next chunk
        if (more) {
            #pragma unroll
            for (int i = 0; i < 4; i++) {
                int idx = tid + i * 256;
                int r = idx >> 3, c4 = idx & 7;
                int mt = r >> 4, ri = r & 15, g = ri & 7;
                int k0 = c4 * 4, ks2 = k0 >> 3;
                int regbase = ((ri >> 3) & 1) | ((k0 & 4) ? 2 : 0);
                uint32_t base = aBaseN + (uint32_t)((mt * 4 + ks2) * 512 + g * 64 + regbase * 4);
                asm volatile("st.shared.b32 [%0], %1;" :: "r"(base +  0), "r"(cvt_tf32(av[i].x)) : "memory");
                asm volatile("st.shared.b32 [%0], %1;" :: "r"(base + 16), "r"(cvt_tf32(av[i].y)) : "memory");
                asm volatile("st.shared.b32 [%0], %1;" :: "r"(base + 32), "r"(cvt_tf32(av[i].z)) : "memory");
                asm volatile("st.shared.b32 [%0], %1;" :: "r"(base + 48), "r"(cvt_tf32(av[i].w)) : "memory");
            }
            #pragma unroll
            for (int i = 0; i < 4; i++) {
                asm volatile("st.shared.v4.b32 [%0], {%1,%2,%3,%4};"
                             :: "r"(bBaseN + (uint32_t)(tid + i * 256) * 16),
                                "r"(__float_as_uint(bv[i].x)), "r"(__float_as_uint(bv[i].y)),
                                "r"(__float_as_uint(bv[i].z)), "r"(__float_as_uint(bv[i].w)) : "memory");
            }
        }
        __syncthreads();
    }

    // ---- epilogue: frags -> smem stage -> coalesced writeback
    float* stage = (float*)(smem + 1024);
    {
        int g = lane >> 2, q = lane & 3;
        #pragma unroll
        for (int mi = 0; mi < 4; mi++) {
            #pragma unroll
            for (int nt = 0; nt < 4; nt++) {
                int r0 = wm * 64 + mi * 16 + g;
                int c  = wc * 32 + nt * 8 + q * 2;
                float2 v01 = make_float2(acc[mi * 4 + nt][0], acc[mi * 4 + nt][1]);
                float2 v23 = make_float2(acc[mi * 4 + nt][2], acc[mi * 4 + nt][3]);
                *(float2*)&stage[r0 * 132 + c]       = v01;
                *(float2*)&stage[(r0 + 8) * 132 + c] = v23;
            }
        }
    }
    __syncthreads();

    {
        #pragma unroll
        for (int i = 0; i < 16; i++) {
            int idx = tid + i * 256;             // f4 index in 128x128
            int row = idx >> 5, c4 = idx & 31;
            long r = rowBlk + row;
            int col = colBlk + c4 * 4;
            float4 v = *(const float4*)&stage[row * 132 + c4 * 4];
            float4 bb = *(const float4*)&bias[col];
            v.x += bb.x; v.y += bb.y; v.z += bb.z; v.w += bb.w;

            if (EPI == 0) {
                *(float4*)&C[r * N + col] = v;
            } else if (EPI == 1) {
                int s  = (int)(r >> 11), n = (int)(r & 2047);
                int hn = s >> 3, wn = s & 7;
                int ij = n >> 5, b2 = n & 31;
                int h  = ((hn << 3) + (ij >> 3) + 4) & 63;
                int w  = ((wn << 3) + (ij & 7) + 4) & 63;
                long dest = ((long)(((h << 6) + w) * 32 + b2)) * 512;
                float4 x0 = *(const float4*)&add1[r * 512 + col];
                float4 s0 = *(const float4*)&add2[dest + col];
                v.x += x0.x + s0.x; v.y += x0.y + s0.y;
                v.z += x0.z + s0.z; v.w += x0.w + s0.w;
                *(float4*)&C[dest + col] = v;
            } else if (EPI == 2) {
                v.x = gelu_exact(v.x); v.y = gelu_exact(v.y);
                v.z = gelu_exact(v.z); v.w = gelu_exact(v.w);
                *(float4*)&C[r * N + col] = v;
            } else {
                float4 h0 = *(const float4*)&add1[r * N + col];
                float4 l0 = *(const float4*)&add2[r * N + col];
                v.x += h0.x + l0.x; v.y += h0.y + l0.y;
                v.z += h0.z + l0.z; v.w += h0.w + l0.w;
                *(float4*)&C[r * N + col] = v;
            }
        }
    }
}

// ---------------------------------------------------------------------------
// Launcher
// ---------------------------------------------------------------------------
extern "C" void kernel_launch(void* const* d_in, const int* in_sizes, int n_in,
                              void* d_out, int out_size)
{
    const float* hs    = (const float*)d_in[0];
    const float* ln1g  = (const float*)d_in[1];
    const float* ln1b  = (const float*)d_in[2];
    const float* wqkv  = (const float*)d_in[3];
    const float* bqkv  = (const float*)d_in[4];
    const float* wproj = (const float*)d_in[5];
    const float* bproj = (const float*)d_in[6];
    const float* ln2g  = (const float*)d_in[7];
    const float* ln2b  = (const float*)d_in[8];
    const float* wfc1  = (const float*)d_in[9];
    const float* bfc1  = (const float*)d_in[10];
    const float* wfc2  = (const float*)d_in[11];
    const float* bfc2  = (const float*)d_in[12];
    float* out = (float*)d_out;

    float *xw, *ctx, *hidden, *ln2buf, *big, *wprep;
    cudaGetSymbolAddress((void**)&xw,     g_xw);
    cudaGetSymbolAddress((void**)&ctx,    g_ctx);
    cudaGetSymbolAddress((void**)&hidden, g_hidden);
    cudaGetSymbolAddress((void**)&ln2buf, g_ln2);
    cudaGetSymbolAddress((void**)&big,    g_big);
    cudaGetSymbolAddress((void**)&wprep,  g_wprep);

    static int smem_set = 0;
    if (!smem_set) {
        cudaFuncSetAttribute(gemm_tc<0>, cudaFuncAttributeMaxDynamicSharedMemorySize, DYN_SMEM);
        cudaFuncSetAttribute(gemm_tc<1>, cudaFuncAttributeMaxDynamicSharedMemorySize, DYN_SMEM);
        cudaFuncSetAttribute(gemm_tc<2>, cudaFuncAttributeMaxDynamicSharedMemorySize, DYN_SMEM);
        cudaFuncSetAttribute(gemm_tc<3>, cudaFuncAttributeMaxDynamicSharedMemorySize, DYN_SMEM);
        smem_set = 1;
    }

    // 0) preformat weights into fragment order
    k_prep<<<dim3(12, 16), 256>>>(wqkv,  wprep + WP_QKV,  1536, 16);
    k_prep<<<dim3(4,  16), 256>>>(wproj, wprep + WP_PROJ, 512,  16);
    k_prep<<<dim3(16, 16), 256>>>(wfc1,  wprep + WP_FC1,  2048, 16);
    k_prep<<<dim3(4,  64), 256>>>(wfc2,  wprep + WP_FC2,  512,  64);

    // 1) LN1 + shift + window partition
    k_ln<<<MROWS, 128>>>(hs, ln1g, ln1b, xw, 1);

    // 2) QKV GEMM
    gemm_tc<0><<<dim3(12, 1024), 256, DYN_SMEM>>>(xw, wprep + WP_QKV, bqkv, big, nullptr, nullptr, 1536, 16);

    // 3) Windowed attention
    k_attn<<<2048 * 16, 256>>>(big, ctx);

    // 4) Proj GEMM + residual + scatter
    gemm_tc<1><<<dim3(4, 1024), 256, DYN_SMEM>>>(ctx, wprep + WP_PROJ, bproj, hidden, xw, hs, 512, 16);

    // 5) LN2
    k_ln<<<MROWS, 128>>>(hidden, ln2g, ln2b, ln2buf, 0);

    // 6) FC1 GEMM + GELU
    gemm_tc<2><<<dim3(16, 1024), 256, DYN_SMEM>>>(ln2buf, wprep + WP_FC1, bfc1, big, nullptr, nullptr, 2048, 16);

    // 7) FC2 GEMM + final residuals
    gemm_tc<3><<<dim3(4, 1024), 256, DYN_SMEM>>>(big, wprep + WP_FC2, bfc2, out, hidden, ln2buf, 512, 64);
}

// round 4
// speedup vs baseline: 2.8626x; 1.3144x over previous
#include <cuda_runtime.h>
#include <math.h>
#include <stdint.h>

// ---------------------------------------------------------------------------
// Problem constants
// ---------------------------------------------------------------------------
#define CSZ     512
#define MROWS   131072      // H*W*B = 4096*32

// ---------------------------------------------------------------------------
// Scratch (static device globals -- no allocations allowed)
// ---------------------------------------------------------------------------
__device__ float g_xw    [(size_t)MROWS * CSZ];     // LN1 out, A-fragment layout (kT=16)
__device__ float g_ctx   [(size_t)MROWS * CSZ];     // attn out, A-fragment layout (kT=16)
__device__ float g_hidden[(size_t)MROWS * CSZ];     // post-attn residual, row-major
__device__ float g_ln2   [(size_t)MROWS * CSZ];     // LN2 out, A-fragment layout (kT=16)
__device__ float g_big   [(size_t)MROWS * 2048];    // qkv row-major(1536) then fc1-out frag (kT=64)
__device__ float g_wprep [512*1536 + 512*512 + 512*2048 + 2048*512];

#define WP_QKV  0
#define WP_PROJ (512*1536)
#define WP_FC1  (WP_PROJ + 512*512)
#define WP_FC2  (WP_FC1 + 512*2048)

// ---------------------------------------------------------------------------
// Helpers
// ---------------------------------------------------------------------------
__device__ __forceinline__ uint32_t smem_u32(const void* p) {
    uint32_t a;
    asm("{ .reg .u64 t; cvta.to.shared.u64 t, %1; cvt.u32.u64 %0, t; }" : "=r"(a) : "l"(p));
    return a;
}
__device__ __forceinline__ uint32_t cvt_tf32(float x) {
    uint32_t r;
    asm("cvt.rna.tf32.f32 %0, %1;" : "=r"(r) : "f"(x));
    return r;
}
__device__ __forceinline__ float tf32r(float x) { return __uint_as_float(cvt_tf32(x)); }

__device__ __forceinline__ void mma_tf32(float* d, uint32_t a0, uint32_t a1, uint32_t a2, uint32_t a3,
                                         uint32_t b0, uint32_t b1)
{
    asm volatile(
        "mma.sync.aligned.m16n8k8.row.col.f32.tf32.tf32.f32 "
        "{%0,%1,%2,%3}, {%4,%5,%6,%7}, {%8,%9}, {%0,%1,%2,%3};"
        : "+f"(d[0]), "+f"(d[1]), "+f"(d[2]), "+f"(d[3])
        : "r"(a0), "r"(a1), "r"(a2), "r"(a3), "r"(b0), "r"(b1));
}
__device__ __forceinline__ void cp_async16(uint32_t dst, const void* src) {
    asm volatile("cp.async.cg.shared.global [%0], [%1], 16;" :: "r"(dst), "l"(src) : "memory");
}
#define CP_COMMIT() asm volatile("cp.async.commit_group;" ::: "memory")
#define CP_WAIT(n)  asm volatile("cp.async.wait_group %0;" :: "n"(n) : "memory")

__device__ __forceinline__ float gelu_exact(float x)
{
    return 0.5f * x * (1.0f + erff(x * 0.70710678118654752f));
}

// A-fragment address (float index) for element (row r, channel c), chunk count kT.
// Blocks of 8192 floats per (rb = r>>8, kt = c>>5); inside: 64 tiles of 128 floats
// (mt = (r&255)>>4, ks = (c>>3)&3); inside tile: g*16 + q*4 + rb2 + 2*hi.
__device__ __forceinline__ size_t fragAddr(long r, int c, int kT) {
    int rm = (int)(r & 255);
    int ri = rm & 15;
    return ((size_t)(r >> 8) * kT + (c >> 5)) * 8192
         + (size_t)(((rm >> 4) * 4 + ((c >> 3) & 3)) * 128
         + (ri & 7) * 16 + (c & 3) * 4 + (ri >> 3) + ((c >> 2) & 1) * 2);
}

// ---------------------------------------------------------------------------
// Weight prep: W[K,N] row-major -> per (ntile j, kchunk kt) 4096-float B-frag
// blocks: offset = ((nb*4+ks)*8+nt)*64 + t*2 + which
//   n_local = nb*64 + nt*8 + (t>>2),  k_local = ks*8 + which*4 + (t&3)
// ---------------------------------------------------------------------------
__global__ __launch_bounds__(256) void k_prep(const float* __restrict__ W,
                                              float* __restrict__ dst,
                                              int N, int kTiles)
{
    int j = blockIdx.x, kt = blockIdx.y;
    float* blk = dst + ((size_t)(j * kTiles + kt)) * 4096;
    for (int f = threadIdx.x; f < 4096; f += 256) {
        int which = f & 1;
        int t  = (f >> 1) & 31;
        int nt = (f >> 6) & 7;
        int ks = (f >> 9) & 3;
        int nb = (f >> 11) & 1;
        int n_local = nb * 64 + nt * 8 + (t >> 2);
        int k_local = ks * 8 + which * 4 + (t & 3);
        float v = W[(size_t)(kt * 32 + k_local) * N + j * 128 + n_local];
        ((uint32_t*)blk)[f] = cvt_tf32(v);
    }
}

// ---------------------------------------------------------------------------
// LayerNorm (+ optional shift/window-partition gather); writes A-frag layout (kT=16)
// ---------------------------------------------------------------------------
__global__ __launch_bounds__(128) void k_ln(const float* __restrict__ x,
                                            const float* __restrict__ g,
                                            const float* __restrict__ b,
                                            float* __restrict__ y,
                                            int permute)
{
    long r = blockIdx.x;
    long src = r;
    if (permute) {
        int s  = (int)(r >> 11), n = (int)(r & 2047);
        int hn = s >> 3, wn = s & 7;
        int ij = n >> 5, bb = n & 31;
        int h  = ((hn << 3) + (ij >> 3) + 4) & 63;
        int w  = ((wn << 3) + (ij & 7) + 4) & 63;
        src = ((h << 6) + w) * 32 + bb;
    }
    int t = threadIdx.x;
    float4 v = ((const float4*)(x + src * CSZ))[t];
    float sum = v.x + v.y + v.z + v.w;
    float sq  = v.x*v.x + v.y*v.y + v.z*v.z + v.w*v.w;
    #pragma unroll
    for (int o = 16; o > 0; o >>= 1) {
        sum += __shfl_xor_sync(0xffffffffu, sum, o);
        sq  += __shfl_xor_sync(0xffffffffu, sq,  o);
    }
    __shared__ float ssum[4], ssq[4];
    int warp = t >> 5, lane = t & 31;
    if (lane == 0) { ssum[warp] = sum; ssq[warp] = sq; }
    __syncthreads();
    float tot = ssum[0] + ssum[1] + ssum[2] + ssum[3];
    float tq  = ssq[0]  + ssq[1]  + ssq[2]  + ssq[3];
    float mu  = tot * (1.0f / 512.0f);
    float var = tq * (1.0f / 512.0f) - mu * mu;
    float inv = rsqrtf(var + 1e-5f);
    float4 gg = ((const float4*)g)[t];
    float4 bb4 = ((const float4*)b)[t];
    float o0 = (v.x - mu) * inv * gg.x + bb4.x;
    float o1 = (v.y - mu) * inv * gg.y + bb4.y;
    float o2 = (v.z - mu) * inv * gg.z + bb4.z;
    float o3 = (v.w - mu) * inv * gg.w + bb4.w;

    // fragment scatter: k = 4t..4t+3
    int rm = (int)(r & 255), ri = rm & 15;
    size_t base = ((size_t)(r >> 8) * 16 + (t >> 3)) * 8192
                + (size_t)(((rm >> 4) * 4 + ((t >> 1) & 3)) * 128
                + (ri & 7) * 16 + (ri >> 3) + (t & 1) * 2);
    y[base + 0]  = tf32r(o0);
    y[base + 4]  = tf32r(o1);
    y[base + 8]  = tf32r(o2);
    y[base + 12] = tf32r(o3);
}

// ---------------------------------------------------------------------------
// Windowed attention (fp32 SIMT); writes ctx in A-frag layout (kT=16)
// ---------------------------------------------------------------------------
__device__ __forceinline__ int regcode(int h) { return h < 56 ? 0 : (h < 60 ? 1 : 2); }

__global__ __launch_bounds__(256) void k_attn(const float* __restrict__ qkv,
                                              float* __restrict__ ctx)
{
    int n  = blockIdx.x >> 4;
    int hd = blockIdx.x & 15;

    __shared__ float sq[64][33], sk[64][33], sv[64][33];
    __shared__ float sp[64][65];

    int tid = threadIdx.x;
    for (int idx = tid; idx < 2048; idx += 256) {
        int s = idx >> 5, d = idx & 31;
        long base = ((long)(s * 2048 + n)) * 1536 + hd * 96 + d;
        sq[s][d] = qkv[base];
        sk[s][d] = qkv[base + 32];
        sv[s][d] = qkv[base + 64];
    }
    __syncthreads();

    int nw = n & 63;
    int s  = tid >> 2;
    int t0 = (tid & 3) << 4;

    float qr[32];
    #pragma unroll
    for (int d = 0; d < 32; d++) qr[d] = sq[s][d];

    int cs = regcode(((nw >> 3) << 3) + (s >> 3)) * 3 + regcode(((nw & 7) << 3) + (s & 7));

    float sc[16];
    float mx = -1e30f;
    #pragma unroll
    for (int tt = 0; tt < 16; tt++) {
        int t = t0 + tt;
        float a = 0.0f;
        #pragma unroll
        for (int d = 0; d < 32; d++) a += qr[d] * sk[t][d];
        a *= 0.17677669529663689f;
        int ct = regcode(((nw >> 3) << 3) + (t >> 3)) * 3 + regcode(((nw & 7) << 3) + (t & 7));
        a = (ct != cs) ? -10000.0f : a;
        sc[tt] = a;
        mx = fmaxf(mx, a);
    }
    mx = fmaxf(mx, __shfl_xor_sync(0xffffffffu, mx, 1));
    mx = fmaxf(mx, __shfl_xor_sync(0xffffffffu, mx, 2));
    float sum = 0.0f;
    #pragma unroll
    for (int tt = 0; tt < 16; tt++) { sc[tt] = expf(sc[tt] - mx); sum += sc[tt]; }
    sum += __shfl_xor_sync(0xffffffffu, sum, 1);
    sum += __shfl_xor_sync(0xffffffffu, sum, 2);
    float inv = 1.0f / sum;
    #pragma unroll
    for (int tt = 0; tt < 16; tt++) sp[s][t0 + tt] = sc[tt] * inv;
    __syncthreads();

    int d0q = tid & 3;          // ks = d0q, k = hd*32 + d0q*8 + d
    float acc[8];
    #pragma unroll
    for (int d = 0; d < 8; d++) acc[d] = 0.0f;
    for (int t = 0; t < 64; t++) {
        float p = sp[s][t];
        #pragma unroll
        for (int d = 0; d < 8; d++) acc[d] += p * sv[t][d0q * 8 + d];
    }
    long r = (long)s * 2048 + n;
    int rm = (int)(r & 255), ri = rm & 15;
    size_t ob = ((size_t)(r >> 8) * 16 + hd) * 8192
              + (size_t)(((rm >> 4) * 4 + d0q) * 128 + (ri & 7) * 16 + (ri >> 3));
    #pragma unroll
    for (int d = 0; d < 8; d++)
        ctx[ob + (d & 3) * 4 + (d >> 2) * 2] = tf32r(acc[d]);
}

// ---------------------------------------------------------------------------
// tf32 mma.sync GEMM: CTA tile 256x128, chunk K=32, 8 warps (4m x 2n) of 64x64.
// Both operands arrive preformatted; mainloop = cp.async + lds + mma only.
//   EPI 0: row-major out = acc + bias                          (QKV, Nout=1536)
//   EPI 1: scatter: C[dest] = acc+bias+xwfrag[r]+add2[dest]    (proj)
//   EPI 2: frag-out(kT=64) = gelu(acc + bias)                  (FC1)
//   EPI 3: row-major out = acc+bias+add1[r]+ln2frag[r]         (FC2 final)
// ---------------------------------------------------------------------------
#define NSTAGE     3
#define STAGE_B    49152                 // 32KB A + 16KB B
#define DYN_SMEM   (NSTAGE * STAGE_B)    // 147456

template <int EPI>
__global__ __launch_bounds__(256, 1) void gemm_tc(const float* __restrict__ A,
                                                  const float* __restrict__ Bprep,
                                                  const float* __restrict__ bias,
                                                  float* __restrict__ C,
                                                  const float* __restrict__ add1,
                                                  const float* __restrict__ add2,
                                                  int Nout, int kTiles)
{
    extern __shared__ char smem[];
    const uint32_t sbase = smem_u32(smem);
    const int tid  = threadIdx.x;
    const int wid  = tid >> 5;
    const int lane = tid & 31;
    const int wm   = wid >> 1;   // 0..3 (64-row band)
    const int wnb  = wid & 1;    // 0..1 (64-col band)

    const long rowBlk = (long)blockIdx.y * 256;
    const int  colBlk = blockIdx.x * 128;
    const float* Ablk = A + (size_t)blockIdx.y * kTiles * 8192;
    const float* Bblk = Bprep + (size_t)blockIdx.x * kTiles * 4096;

    float acc[4][8][4];
    #pragma unroll
    for (int mi = 0; mi < 4; mi++)
        #pragma unroll
        for (int nt = 0; nt < 8; nt++)
            #pragma unroll
            for (int j = 0; j < 4; j++) acc[mi][nt][j] = 0.0f;

    // --- async stage issue ---
    auto issue = [&](int kt) {
        uint32_t aB = sbase + (kt % NSTAGE) * STAGE_B;
        uint32_t bB = aB + 32768;
        const float* as = Ablk + (size_t)kt * 8192;
        const float* bs = Bblk + (size_t)kt * 4096;
        #pragma unroll
        for (int i = 0; i < 8; i++)
            cp_async16(aB + (uint32_t)(tid + i * 256) * 16, as + (size_t)(tid + i * 256) * 4);
        #pragma unroll
        for (int i = 0; i < 4; i++)
            cp_async16(bB + (uint32_t)(tid + i * 256) * 16, bs + (size_t)(tid + i * 256) * 4);
        CP_COMMIT();
    };

    issue(0);
    issue(1);

    for (int kt = 0; kt < kTiles; kt++) {
        if (kt == kTiles - 1) { CP_WAIT(0); } else { CP_WAIT(1); }
        __syncthreads();
        if (kt + 2 < kTiles) issue(kt + 2);

        const uint32_t aB = sbase + (kt % NSTAGE) * STAGE_B;
        const uint32_t bB = aB + 32768;

        #pragma unroll
        for (int ks = 0; ks < 4; ks++) {
            uint32_t afr[4][4];
            #pragma unroll
            for (int mi = 0; mi < 4; mi++) {
                uint32_t addr = aB + (uint32_t)(((wm * 4 + mi) * 4 + ks) * 512 + lane * 16);
                asm volatile("ld.shared.v4.b32 {%0,%1,%2,%3}, [%4];"
                             : "=r"(afr[mi][0]), "=r"(afr[mi][1]), "=r"(afr[mi][2]), "=r"(afr[mi][3])
                             : "r"(addr));
            }
            uint32_t bfr[8][2];
            #pragma unroll
            for (int nt = 0; nt < 8; nt++) {
                uint32_t addr = bB + (uint32_t)((((wnb * 4 + ks) * 8 + nt) * 64 + lane * 2) * 4);
                asm volatile("ld.shared.v2.b32 {%0,%1}, [%2];"
                             : "=r"(bfr[nt][0]), "=r"(bfr[nt][1]) : "r"(addr));
            }
            #pragma unroll
            for (int mi = 0; mi < 4; mi++)
                #pragma unroll
                for (int nt = 0; nt < 8; nt++)
                    mma_tf32(acc[mi][nt], afr[mi][0], afr[mi][1], afr[mi][2], afr[mi][3],
                             bfr[nt][0], bfr[nt][1]);
        }
    }

    // ---- epilogue: direct fragment writeback (no smem) ----
    const int g  = lane >> 2;
    const int q2 = lane & 3;

    float2 bs2[8];
    #pragma unroll
    for (int nt = 0; nt < 8; nt++)
        bs2[nt] = *(const float2*)&bias[colBlk + wnb * 64 + nt * 8 + q2 * 2];

    #pragma unroll
    for (int mi = 0; mi < 4; mi++) {
        long r = rowBlk + wm * 64 + mi * 16 + g;   // ri<8; r+8 is partner row

        long d0 = 0, d1 = 0;
        if (EPI == 1) {
            {
                int s = (int)(r >> 11), n = (int)(r & 2047);
                int hn = s >> 3, wn2 = s & 7;
                int ij = n >> 5, b2 = n & 31;
                int h = ((hn << 3) + (ij >> 3) + 4) & 63;
                int w = ((wn2 << 3) + (ij & 7) + 4) & 63;
                d0 = ((long)(((h << 6) + w) * 32 + b2)) * 512;
            }
            {
                long r8 = r + 8;
                int s = (int)(r8 >> 11), n = (int)(r8 & 2047);
                int hn = s >> 3, wn2 = s & 7;
                int ij = n >> 5, b2 = n & 31;
                int h = ((hn << 3) + (ij >> 3) + 4) & 63;
                int w = ((wn2 << 3) + (ij & 7) + 4) & 63;
                d1 = ((long)(((h << 6) + w) * 32 + b2)) * 512;
            }
        }

        #pragma unroll
        for (int nt = 0; nt < 8; nt++) {
            int c = colBlk + wnb * 64 + nt * 8 + q2 * 2;
            float v00 = acc[mi][nt][0] + bs2[nt].x;   // (r,   c)
            float v01 = acc[mi][nt][1] + bs2[nt].y;   // (r,   c+1)
            float v10 = acc[mi][nt][2] + bs2[nt].x;   // (r+8, c)
            float v11 = acc[mi][nt][3] + bs2[nt].y;   // (r+8, c+1)

            if (EPI == 0) {
                *(float2*)&C[r * Nout + c]       = make_float2(v00, v01);
                *(float2*)&C[(r + 8) * Nout + c] = make_float2(v10, v11);
            } else if (EPI == 1) {
                float2 x0 = *(const float2*)&add1[fragAddr(r, c, 16)];      // xw (r,c),(r+8,c)
                float2 x1 = *(const float2*)&add1[fragAddr(r, c + 1, 16)];
                float2 s0 = *(const float2*)&add2[d0 + c];
                float2 s1 = *(const float2*)&add2[d1 + c];
                v00 += x0.x + s0.x; v01 += x1.x + s0.y;
                v10 += x0.y + s1.x; v11 += x1.y + s1.y;
                *(float2*)&C[d0 + c] = make_float2(v00, v01);
                *(float2*)&C[d1 + c] = make_float2(v10, v11);
            } else if (EPI == 2) {
                v00 = tf32r(gelu_exact(v00)); v01 = tf32r(gelu_exact(v01));
                v10 = tf32r(gelu_exact(v10)); v11 = tf32r(gelu_exact(v11));
                *(float2*)&C[fragAddr(r, c, 64)]     = make_float2(v00, v10);
                *(float2*)&C[fragAddr(r, c + 1, 64)] = make_float2(v01, v11);
            } else {
                float2 h0 = *(const float2*)&add1[r * 512 + c];
                float2 h1 = *(const float2*)&add1[(r + 8) * 512 + c];
                float2 l0 = *(const float2*)&add2[fragAddr(r, c, 16)];      // ln2 (r,c),(r+8,c)
                float2 l1 = *(const float2*)&add2[fragAddr(r, c + 1, 16)];
                v00 += h0.x + l0.x; v01 += h0.y + l1.x;
                v10 += h1.x + l0.y; v11 += h1.y + l1.y;
                *(float2*)&C[r * 512 + c]       = make_float2(v00, v01);
                *(float2*)&C[(r + 8) * 512 + c] = make_float2(v10, v11);
            }
        }
    }
}

// ---------------------------------------------------------------------------
// Launcher
// ---------------------------------------------------------------------------
extern "C" void kernel_launch(void* const* d_in, const int* in_sizes, int n_in,
                              void* d_out, int out_size)
{
    const float* hs    = (const float*)d_in[0];
    const float* ln1g  = (const float*)d_in[1];
    const float* ln1b  = (const float*)d_in[2];
    const float* wqkv  = (const float*)d_in[3];
    const float* bqkv  = (const float*)d_in[4];
    const float* wproj = (const float*)d_in[5];
    const float* bproj = (const float*)d_in[6];
    const float* ln2g  = (const float*)d_in[7];
    const float* ln2b  = (const float*)d_in[8];
    const float* wfc1  = (const float*)d_in[9];
    const float* bfc1  = (const float*)d_in[10];
    const float* wfc2  = (const float*)d_in[11];
    const float* bfc2  = (const float*)d_in[12];
    float* out = (float*)d_out;

    float *xw, *ctx, *hidden, *ln2buf, *big, *wprep;
    cudaGetSymbolAddress((void**)&xw,     g_xw);
    cudaGetSymbolAddress((void**)&ctx,    g_ctx);
    cudaGetSymbolAddress((void**)&hidden, g_hidden);
    cudaGetSymbolAddress((void**)&ln2buf, g_ln2);
    cudaGetSymbolAddress((void**)&big,    g_big);
    cudaGetSymbolAddress((void**)&wprep,  g_wprep);

    static int smem_set = 0;
    if (!smem_set) {
        cudaFuncSetAttribute(gemm_tc<0>, cudaFuncAttributeMaxDynamicSharedMemorySize, DYN_SMEM);
        cudaFuncSetAttribute(gemm_tc<1>, cudaFuncAttributeMaxDynamicSharedMemorySize, DYN_SMEM);
        cudaFuncSetAttribute(gemm_tc<2>, cudaFuncAttributeMaxDynamicSharedMemorySize, DYN_SMEM);
        cudaFuncSetAttribute(gemm_tc<3>, cudaFuncAttributeMaxDynamicSharedMemorySize, DYN_SMEM);
        smem_set = 1;
    }

    // 0) preformat weights into B-fragment blocks
    k_prep<<<dim3(12, 16), 256>>>(wqkv,  wprep + WP_QKV,  1536, 16);
    k_prep<<<dim3(4,  16), 256>>>(wproj, wprep + WP_PROJ, 512,  16);
    k_prep<<<dim3(16, 16), 256>>>(wfc1,  wprep + WP_FC1,  2048, 16);
    k_prep<<<dim3(4,  64), 256>>>(wfc2,  wprep + WP_FC2,  512,  64);

    // 1) LN1 + shift + window partition -> xw (frag)
    k_ln<<<MROWS, 128>>>(hs, ln1g, ln1b, xw, 1);

    // 2) QKV GEMM: row-major out
    gemm_tc<0><<<dim3(12, 512), 256, DYN_SMEM>>>(xw, wprep + WP_QKV, bqkv, big,
                                                 nullptr, nullptr, 1536, 16);

    // 3) Windowed attention -> ctx (frag)
    k_attn<<<2048 * 16, 256>>>(big, ctx);

    // 4) Proj GEMM + residual + window-reverse scatter -> hidden (row-major)
    gemm_tc<1><<<dim3(4, 512), 256, DYN_SMEM>>>(ctx, wprep + WP_PROJ, bproj, hidden,
                                                xw, hs, 512, 16);

    // 5) LN2 -> ln2buf (frag)
    k_ln<<<MROWS, 128>>>(hidden, ln2g, ln2b, ln2buf, 0);

    // 6) FC1 GEMM + GELU -> big (frag, kT=64)
    gemm_tc<2><<<dim3(16, 512), 256, DYN_SMEM>>>(ln2buf, wprep + WP_FC1, bfc1, big,
                                                 nullptr, nullptr, 2048, 16);

    // 7) FC2 GEMM + final residuals -> out (row-major)
    gemm_tc<3><<<dim3(4, 512), 256, DYN_SMEM>>>(big, wprep + WP_FC2, bfc2, out,
                                                hidden, ln2buf, 512, 64);
}

// round 5
// speedup vs baseline: 4.2044x; 1.4687x over previous
#include <cuda_runtime.h>
#include <cuda_fp16.h>
#include <math.h>
#include <stdint.h>

// ---------------------------------------------------------------------------
// Problem constants
// ---------------------------------------------------------------------------
#define CSZ     512
#define MROWS   131072      // H*W*B = 4096*32

// ---------------------------------------------------------------------------
// Scratch (static device globals -- no allocations allowed)
// ---------------------------------------------------------------------------
__device__ __half g_xw    [(size_t)MROWS * CSZ];    // LN1 out, A-frag half (kT=16)
__device__ __half g_ctx   [(size_t)MROWS * CSZ];    // attn out, A-frag half (kT=16)
__device__ float  g_hidden[(size_t)MROWS * CSZ];    // post-attn residual, row-major fp32
__device__ __half g_ln2   [(size_t)MROWS * CSZ];    // LN2 out, A-frag half (kT=16)
__device__ __half g_big   [(size_t)MROWS * 2048];   // qkv row-major half(1536); fc1-out frag (kT=64)
__device__ __half g_wprep [512*1536 + 512*512 + 512*2048 + 2048*512];

#define WP_QKV  0
#define WP_PROJ (512*1536)
#define WP_FC1  (WP_PROJ + 512*512)
#define WP_FC2  (WP_FC1 + 512*2048)

// ---------------------------------------------------------------------------
// Helpers
// ---------------------------------------------------------------------------
__device__ __forceinline__ uint32_t smem_u32(const void* p) {
    uint32_t a;
    asm("{ .reg .u64 t; cvta.to.shared.u64 t, %1; cvt.u32.u64 %0, t; }" : "=r"(a) : "l"(p));
    return a;
}
__device__ __forceinline__ void mma_f16(float* d, uint32_t a0, uint32_t a1, uint32_t a2, uint32_t a3,
                                        uint32_t b0, uint32_t b1)
{
    asm volatile(
        "mma.sync.aligned.m16n8k16.row.col.f32.f16.f16.f32 "
        "{%0,%1,%2,%3}, {%4,%5,%6,%7}, {%8,%9}, {%0,%1,%2,%3};"
        : "+f"(d[0]), "+f"(d[1]), "+f"(d[2]), "+f"(d[3])
        : "r"(a0), "r"(a1), "r"(a2), "r"(a3), "r"(b0), "r"(b1));
}
__device__ __forceinline__ void cp_async16(uint32_t dst, const void* src) {
    asm volatile("cp.async.cg.shared.global [%0], [%1], 16;" :: "r"(dst), "l"(src) : "memory");
}
#define CP_COMMIT() asm volatile("cp.async.commit_group;" ::: "memory")
#define CP_WAIT(n)  asm volatile("cp.async.wait_group %0;" :: "n"(n) : "memory")

__device__ __forceinline__ float gelu_exact(float x)
{
    return 0.5f * x * (1.0f + erff(x * 0.70710678118654752f));
}

// Half A-fragment address (half index) for element (row r, channel c), kT chunks.
// Chunk block = 256 rows x 32 ch = 8192 halves. Inside: 32 tiles (mt*2+ks2) of
// 256 halves; per-lane 8 halves: [khi*4 + hi*2 + klo], lane = g*4 + q.
__device__ __forceinline__ size_t fragAddrH(long r, int c, int kT) {
    int rm = (int)(r & 255);
    int ri = rm & 15;
    int k  = c & 31;
    return ((size_t)(r >> 8) * kT + (c >> 5)) * 8192
         + (size_t)(((((rm >> 4) * 2 + (k >> 4)) * 32) + (ri & 7) * 4 + ((k >> 1) & 3)) * 8
         + ((k >> 3) & 1) * 4 + (ri >> 3) * 2 + (k & 1));
}

// ---------------------------------------------------------------------------
// Weight prep: W[K,N] fp32 row-major -> per (ntile j, kchunk kt) 4096-half B-frag
// blocks: half offset = ((nt*32 + g*4 + q)*8) + reg*2 + klo
//   n_local = nt*8 + g,  k_local = reg*8 + q*2 + klo
// ---------------------------------------------------------------------------
__global__ __launch_bounds__(256) void k_prep(const float* __restrict__ W,
                                              __half* __restrict__ dst,
                                              int N, int kTiles)
{
    int j = blockIdx.x, kt = blockIdx.y;
    __half* blk = dst + ((size_t)(j * kTiles + kt)) * 4096;
    for (int f = threadIdx.x; f < 4096; f += 256) {
        int klo = f & 1;
        int reg = (f >> 1) & 3;
        int lanep = (f >> 3) & 31;
        int q = lanep & 3, g = lanep >> 2;
        int nt = f >> 8;
        int n_local = nt * 8 + g;
        int k_local = reg * 8 + q * 2 + klo;
        blk[f] = __float2half_rn(W[(size_t)(kt * 32 + k_local) * N + j * 128 + n_local]);
    }
}

// ---------------------------------------------------------------------------
// LayerNorm (+ optional shift/window-partition gather); writes half A-frag (kT=16)
// ---------------------------------------------------------------------------
__global__ __launch_bounds__(128) void k_ln(const float* __restrict__ x,
                                            const float* __restrict__ g,
                                            const float* __restrict__ b,
                                            __half* __restrict__ y,
                                            int permute)
{
    long r = blockIdx.x;
    long src = r;
    if (permute) {
        int s  = (int)(r >> 11), n = (int)(r & 2047);
        int hn = s >> 3, wn = s & 7;
        int ij = n >> 5, bb = n & 31;
        int h  = ((hn << 3) + (ij >> 3) + 4) & 63;
        int w  = ((wn << 3) + (ij & 7) + 4) & 63;
        src = ((h << 6) + w) * 32 + bb;
    }
    int t = threadIdx.x;
    float4 v = ((const float4*)(x + src * CSZ))[t];
    float sum = v.x + v.y + v.z + v.w;
    float sq  = v.x*v.x + v.y*v.y + v.z*v.z + v.w*v.w;
    #pragma unroll
    for (int o = 16; o > 0; o >>= 1) {
        sum += __shfl_xor_sync(0xffffffffu, sum, o);
        sq  += __shfl_xor_sync(0xffffffffu, sq,  o);
    }
    __shared__ float ssum[4], ssq[4];
    int warp = t >> 5, lane = t & 31;
    if (lane == 0) { ssum[warp] = sum; ssq[warp] = sq; }
    __syncthreads();
    float tot = ssum[0] + ssum[1] + ssum[2] + ssum[3];
    float tq  = ssq[0]  + ssq[1]  + ssq[2]  + ssq[3];
    float mu  = tot * (1.0f / 512.0f);
    float var = tq * (1.0f / 512.0f) - mu * mu;
    float inv = rsqrtf(var + 1e-5f);
    float4 gg = ((const float4*)g)[t];
    float4 bb4 = ((const float4*)b)[t];
    float o0 = (v.x - mu) * inv * gg.x + bb4.x;
    float o1 = (v.y - mu) * inv * gg.y + bb4.y;
    float o2 = (v.z - mu) * inv * gg.z + bb4.z;
    float o3 = (v.w - mu) * inv * gg.w + bb4.w;

    size_t a0 = fragAddrH(r, 4 * t, 16);
    size_t a1 = fragAddrH(r, 4 * t + 2, 16);
    *(__half2*)&y[a0] = __floats2half2_rn(o0, o1);
    *(__half2*)&y[a1] = __floats2half2_rn(o2, o3);
}

// ---------------------------------------------------------------------------
// Windowed attention (fp32 SIMT, half I/O); writes ctx in half A-frag (kT=16)
// ---------------------------------------------------------------------------
__device__ __forceinline__ int regcode(int h) { return h < 56 ? 0 : (h < 60 ? 1 : 2); }

__global__ __launch_bounds__(256) void k_attn(const __half* __restrict__ qkv,
                                              __half* __restrict__ ctx)
{
    int n  = blockIdx.x >> 4;
    int hd = blockIdx.x & 15;

    __shared__ float sq[64][33], sk[64][33], sv[64][33];
    __shared__ float sp[64][65];

    int tid = threadIdx.x;
    for (int idx = tid; idx < 1024; idx += 256) {
        int s = idx >> 4, dd = (idx & 15) * 2;
        size_t base = ((size_t)(s * 2048 + n)) * 1536 + hd * 96 + dd;
        float2 q2 = __half22float2(*(const __half2*)&qkv[base]);
        float2 k2 = __half22float2(*(const __half2*)&qkv[base + 32]);
        float2 v2 = __half22float2(*(const __half2*)&qkv[base + 64]);
        sq[s][dd] = q2.x; sq[s][dd + 1] = q2.y;
        sk[s][dd] = k2.x; sk[s][dd + 1] = k2.y;
        sv[s][dd] = v2.x; sv[s][dd + 1] = v2.y;
    }
    __syncthreads();

    int nw = n & 63;
    int s  = tid >> 2;
    int t0 = (tid & 3) << 4;

    float qr[32];
    #pragma unroll
    for (int d = 0; d < 32; d++) qr[d] = sq[s][d];

    int cs = regcode(((nw >> 3) << 3) + (s >> 3)) * 3 + regcode(((nw & 7) << 3) + (s & 7));

    float sc[16];
    float mx = -1e30f;
    #pragma unroll
    for (int tt = 0; tt < 16; tt++) {
        int t = t0 + tt;
        float a = 0.0f;
        #pragma unroll
        for (int d = 0; d < 32; d++) a += qr[d] * sk[t][d];
        a *= 0.17677669529663689f;
        int ct = regcode(((nw >> 3) << 3) + (t >> 3)) * 3 + regcode(((nw & 7) << 3) + (t & 7));
        a = (ct != cs) ? -10000.0f : a;
        sc[tt] = a;
        mx = fmaxf(mx, a);
    }
    mx = fmaxf(mx, __shfl_xor_sync(0xffffffffu, mx, 1));
    mx = fmaxf(mx, __shfl_xor_sync(0xffffffffu, mx, 2));
    float sum = 0.0f;
    #pragma unroll
    for (int tt = 0; tt < 16; tt++) { sc[tt] = expf(sc[tt] - mx); sum += sc[tt]; }
    sum += __shfl_xor_sync(0xffffffffu, sum, 1);
    sum += __shfl_xor_sync(0xffffffffu, sum, 2);
    float inv = 1.0f / sum;
    #pragma unroll
    for (int tt = 0; tt < 16; tt++) sp[s][t0 + tt] = sc[tt] * inv;
    __syncthreads();

    int d0q = tid & 3;          // channel base = hd*32 + d0q*8
    float acc[8];
    #pragma unroll
    for (int d = 0; d < 8; d++) acc[d] = 0.0f;
    for (int t = 0; t < 64; t++) {
        float p = sp[s][t];
        #pragma unroll
        for (int d = 0; d < 8; d++) acc[d] += p * sv[t][d0q * 8 + d];
    }
    long r = (long)s * 2048 + n;
    int cb = hd * 32 + d0q * 8;
    #pragma unroll
    for (int ii = 0; ii < 4; ii++) {
        size_t a = fragAddrH(r, cb + 2 * ii, 16);
        *(__half2*)&ctx[a] = __floats2half2_rn(acc[2 * ii], acc[2 * ii + 1]);
    }
}

// ---------------------------------------------------------------------------
// fp16 mma.sync GEMM: CTA tile 256x128, chunk K=32, 8 warps (4m x 2n) of 64x64.
//   EPI 0: half row-major out = acc + bias                     (QKV, Nout=1536)
//   EPI 1: scatter fp32: C[dest]=acc+bias+xwfrag[r]+hs[dest]   (proj)
//   EPI 2: half frag out (kT=64) = gelu(acc + bias)            (FC1)
//   EPI 3: fp32 row-major out = acc+bias+hidden[r]+ln2frag[r]  (FC2 final)
// ---------------------------------------------------------------------------
#define NSTAGE     4
#define STAGE_B    24576                 // 16KB A + 8KB B
#define DYN_SMEM   (NSTAGE * STAGE_B)    // 98304

template <int EPI>
__global__ __launch_bounds__(256, 1) void gemm_tc(const __half* __restrict__ A,
                                                  const __half* __restrict__ Bprep,
                                                  const float* __restrict__ bias,
                                                  void* __restrict__ Cout,
                                                  const void* __restrict__ add1,
                                                  const void* __restrict__ add2,
                                                  int Nout, int kTiles)
{
    extern __shared__ char smem[];
    const uint32_t sbase = smem_u32(smem);
    const int tid  = threadIdx.x;
    const int wid  = tid >> 5;
    const int lane = tid & 31;
    const int wm   = wid >> 1;   // 0..3 (64-row band)
    const int wnb  = wid & 1;    // 0..1 (64-col band)

    const long rowBlk = (long)blockIdx.y * 256;
    const int  colBlk = blockIdx.x * 128;
    const __half* Ablk = A + (size_t)blockIdx.y * kTiles * 8192;
    const __half* Bblk = Bprep + (size_t)blockIdx.x * kTiles * 4096;

    float acc[4][8][4];
    #pragma unroll
    for (int mi = 0; mi < 4; mi++)
        #pragma unroll
        for (int nt = 0; nt < 8; nt++)
            #pragma unroll
            for (int j = 0; j < 4; j++) acc[mi][nt][j] = 0.0f;

    auto issue = [&](int kt) {
        uint32_t aB = sbase + (kt % NSTAGE) * STAGE_B;
        uint32_t bB = aB + 16384;
        const __half* as = Ablk + (size_t)kt * 8192;
        const __half* bs = Bblk + (size_t)kt * 4096;
        #pragma unroll
        for (int i = 0; i < 4; i++)
            cp_async16(aB + (uint32_t)(tid + i * 256) * 16, as + (size_t)(tid + i * 256) * 8);
        #pragma unroll
        for (int i = 0; i < 2; i++)
            cp_async16(bB + (uint32_t)(tid + i * 256) * 16, bs + (size_t)(tid + i * 256) * 8);
        CP_COMMIT();
    };

    issue(0); issue(1); issue(2);

    for (int kt = 0; kt < kTiles; kt++) {
        if (kt < kTiles - 2)      { CP_WAIT(2); }
        else if (kt == kTiles - 2){ CP_WAIT(1); }
        else                      { CP_WAIT(0); }
        __syncthreads();
        if (kt + 3 < kTiles) issue(kt + 3);

        const uint32_t aB = sbase + (kt % NSTAGE) * STAGE_B;
        const uint32_t bB = aB + 16384;

        // B: one lds.128 per nt covers both k16 halves
        uint32_t bfr[8][4];
        #pragma unroll
        for (int nt = 0; nt < 8; nt++) {
            uint32_t addr = bB + (uint32_t)(((wnb * 8 + nt) * 32 + lane) * 16);
            asm volatile("ld.shared.v4.b32 {%0,%1,%2,%3}, [%4];"
                         : "=r"(bfr[nt][0]), "=r"(bfr[nt][1]), "=r"(bfr[nt][2]), "=r"(bfr[nt][3])
                         : "r"(addr));
        }
        #pragma unroll
        for (int ks2 = 0; ks2 < 2; ks2++) {
            uint32_t afr[4][4];
            #pragma unroll
            for (int mi = 0; mi < 4; mi++) {
                uint32_t addr = aB + (uint32_t)((((wm * 4 + mi) * 2 + ks2) * 32 + lane) * 16);
                asm volatile("ld.shared.v4.b32 {%0,%1,%2,%3}, [%4];"
                             : "=r"(afr[mi][0]), "=r"(afr[mi][1]), "=r"(afr[mi][2]), "=r"(afr[mi][3])
                             : "r"(addr));
            }
            #pragma unroll
            for (int mi = 0; mi < 4; mi++)
                #pragma unroll
                for (int nt = 0; nt < 8; nt++)
                    mma_f16(acc[mi][nt], afr[mi][0], afr[mi][1], afr[mi][2], afr[mi][3],
                            bfr[nt][ks2 * 2], bfr[nt][ks2 * 2 + 1]);
        }
    }

    // ---- epilogue: direct fragment writeback ----
    const int g  = lane >> 2;
    const int q2 = lane & 3;

    float2 bs2[8];
    #pragma unroll
    for (int nt = 0; nt < 8; nt++)
        bs2[nt] = *(const float2*)&bias[colBlk + wnb * 64 + nt * 8 + q2 * 2];

    #pragma unroll
    for (int mi = 0; mi < 4; mi++) {
        long r = rowBlk + wm * 64 + mi * 16 + g;   // partner row r+8

        long d0 = 0, d1 = 0;
        if (EPI == 1) {
            {
                int s = (int)(r >> 11), n = (int)(r & 2047);
                int hn = s >> 3, wn2 = s & 7;
                int ij = n >> 5, b2 = n & 31;
                int h = ((hn << 3) + (ij >> 3) + 4) & 63;
                int w = ((wn2 << 3) + (ij & 7) + 4) & 63;
                d0 = ((long)(((h << 6) + w) * 32 + b2)) * 512;
            }
            {
                long r8 = r + 8;
                int s = (int)(r8 >> 11), n = (int)(r8 & 2047);
                int hn = s >> 3, wn2 = s & 7;
                int ij = n >> 5, b2 = n & 31;
                int h = ((hn << 3) + (ij >> 3) + 4) & 63;
                int w = ((wn2 << 3) + (ij & 7) + 4) & 63;
                d1 = ((long)(((h << 6) + w) * 32 + b2)) * 512;
            }
        }

        #pragma unroll
        for (int nt = 0; nt < 8; nt++) {
            int c = colBlk + wnb * 64 + nt * 8 + q2 * 2;
            float v00 = acc[mi][nt][0] + bs2[nt].x;   // (r,   c)
            float v01 = acc[mi][nt][1] + bs2[nt].y;   // (r,   c+1)
            float v10 = acc[mi][nt][2] + bs2[nt].x;   // (r+8, c)
            float v11 = acc[mi][nt][3] + bs2[nt].y;   // (r+8, c+1)

            if (EPI == 0) {
                __half* Ch = (__half*)Cout;
                *(__half2*)&Ch[r * Nout + c]       = __floats2half2_rn(v00, v01);
                *(__half2*)&Ch[(r + 8) * Nout + c] = __floats2half2_rn(v10, v11);
            } else if (EPI == 1) {
                float* Cf = (float*)Cout;
                const __half* xwH = (const __half*)add1;
                const float*  hsF = (const float*)add2;
                size_t a = fragAddrH(r, c, 16);
                float2 x01 = __half22float2(*(const __half2*)&xwH[a]);      // (r,c),(r,c+1)
                float2 x89 = __half22float2(*(const __half2*)&xwH[a + 2]);  // (r+8,c),(r+8,c+1)
                float2 s0 = *(const float2*)&hsF[d0 + c];
                float2 s1 = *(const float2*)&hsF[d1 + c];
                v00 += x01.x + s0.x; v01 += x01.y + s0.y;
                v10 += x89.x + s1.x; v11 += x89.y + s1.y;
                *(float2*)&Cf[d0 + c] = make_float2(v00, v01);
                *(float2*)&Cf[d1 + c] = make_float2(v10, v11);
            } else if (EPI == 2) {
                __half* Ch = (__half*)Cout;
                size_t a = fragAddrH(r, c, 64);
                *(__half2*)&Ch[a]     = __floats2half2_rn(gelu_exact(v00), gelu_exact(v01));
                *(__half2*)&Ch[a + 2] = __floats2half2_rn(gelu_exact(v10), gelu_exact(v11));
            } else {
                float* Cf = (float*)Cout;
                const float*  hF  = (const float*)add1;
                const __half* lnH = (const __half*)add2;
                size_t a = fragAddrH(r, c, 16);
                float2 l01 = __half22float2(*(const __half2*)&lnH[a]);
                float2 l89 = __half22float2(*(const __half2*)&lnH[a + 2]);
                float2 h0 = *(const float2*)&hF[r * 512 + c];
                float2 h1 = *(const float2*)&hF[(r + 8) * 512 + c];
                v00 += h0.x + l01.x; v01 += h0.y + l01.y;
                v10 += h1.x + l89.x; v11 += h1.y + l89.y;
                *(float2*)&Cf[r * 512 + c]       = make_float2(v00, v01);
                *(float2*)&Cf[(r + 8) * 512 + c] = make_float2(v10, v11);
            }
        }
    }
}

// ---------------------------------------------------------------------------
// Launcher
// ---------------------------------------------------------------------------
extern "C" void kernel_launch(void* const* d_in, const int* in_sizes, int n_in,
                              void* d_out, int out_size)
{
    const float* hs    = (const float*)d_in[0];
    const float* ln1g  = (const float*)d_in[1];
    const float* ln1b  = (const float*)d_in[2];
    const float* wqkv  = (const float*)d_in[3];
    const float* bqkv  = (const float*)d_in[4];
    const float* wproj = (const float*)d_in[5];
    const float* bproj = (const float*)d_in[6];
    const float* ln2g  = (const float*)d_in[7];
    const float* ln2b  = (const float*)d_in[8];
    const float* wfc1  = (const float*)d_in[9];
    const float* bfc1  = (const float*)d_in[10];
    const float* wfc2  = (const float*)d_in[11];
    const float* bfc2  = (const float*)d_in[12];
    float* out = (float*)d_out;

    __half *xw, *ctx, *ln2buf, *big, *wprep;
    float *hidden;
    cudaGetSymbolAddress((void**)&xw,     g_xw);
    cudaGetSymbolAddress((void**)&ctx,    g_ctx);
    cudaGetSymbolAddress((void**)&hidden, g_hidden);
    cudaGetSymbolAddress((void**)&ln2buf, g_ln2);
    cudaGetSymbolAddress((void**)&big,    g_big);
    cudaGetSymbolAddress((void**)&wprep,  g_wprep);

    static int smem_set = 0;
    if (!smem_set) {
        cudaFuncSetAttribute(gemm_tc<0>, cudaFuncAttributeMaxDynamicSharedMemorySize, DYN_SMEM);
        cudaFuncSetAttribute(gemm_tc<1>, cudaFuncAttributeMaxDynamicSharedMemorySize, DYN_SMEM);
        cudaFuncSetAttribute(gemm_tc<2>, cudaFuncAttributeMaxDynamicSharedMemorySize, DYN_SMEM);
        cudaFuncSetAttribute(gemm_tc<3>, cudaFuncAttributeMaxDynamicSharedMemorySize, DYN_SMEM);
        smem_set = 1;
    }

    // 0) preformat weights into half B-fragment blocks
    k_prep<<<dim3(12, 16), 256>>>(wqkv,  wprep + WP_QKV,  1536, 16);
    k_prep<<<dim3(4,  16), 256>>>(wproj, wprep + WP_PROJ, 512,  16);
    k_prep<<<dim3(16, 16), 256>>>(wfc1,  wprep + WP_FC1,  2048, 16);
    k_prep<<<dim3(4,  64), 256>>>(wfc2,  wprep + WP_FC2,  512,  64);

    // 1) LN1 + shift + window partition -> xw (half frag)
    k_ln<<<MROWS, 128>>>(hs, ln1g, ln1b, xw, 1);

    // 2) QKV GEMM -> big (half row-major, 1536)
    gemm_tc<0><<<dim3(12, 512), 256, DYN_SMEM>>>(xw, wprep + WP_QKV, bqkv, big,
                                                 nullptr, nullptr, 1536, 16);

    // 3) Windowed attention -> ctx (half frag)
    k_attn<<<2048 * 16, 256>>>(big, ctx);

    // 4) Proj GEMM + residual + window-reverse scatter -> hidden (fp32 row-major)
    gemm_tc<1><<<dim3(4, 512), 256, DYN_SMEM>>>(ctx, wprep + WP_PROJ, bproj, hidden,
                                                xw, hs, 512, 16);

    // 5) LN2 -> ln2buf (half frag)
    k_ln<<<MROWS, 128>>>(hidden, ln2g, ln2b, ln2buf, 0);

    // 6) FC1 GEMM + GELU -> big (half frag, kT=64)
    gemm_tc<2><<<dim3(16, 512), 256, DYN_SMEM>>>(ln2buf, wprep + WP_FC1, bfc1, big,
                                                 nullptr, nullptr, 2048, 16);

    // 7) FC2 GEMM + final residuals -> out (fp32 row-major)
    gemm_tc<3><<<dim3(4, 512), 256, DYN_SMEM>>>(big, wprep + WP_FC2, bfc2, out,
                                                hidden, ln2buf, 512, 64);
}